// round 1
// baseline (speedup 1.0000x reference)
#include <cuda_runtime.h>
#include <math.h>

// ---------------- problem constants ----------------
static constexpr int B_   = 8;
static constexpr int H_   = 128;
static constexpr int W_   = 200;
static constexpr int HW_  = H_ * W_;          // 25600
static constexpr int C1   = 48;               // main channel count
static constexpr int C2   = 64;               // inner channel count
static constexpr int D1_  = C1 * HW_;         // 1228800 (flattened per-batch dim)
static constexpr int BD1_ = B_ * D1_;         // 9830400
static constexpr int BD2_ = B_ * C2 * HW_;    // 13107200
static constexpr int MH   = 5;                // Anderson history
static constexpr int MAXIT = 25;
static constexpr float EPS_ = 1e-5f;

// ---------------- scratch (device globals; no allocation allowed) ----------
__device__ float g_X[(size_t)MH * BD1_];
__device__ float g_F[(size_t)MH * BD1_];
__device__ float g_h[BD1_];
__device__ float g_t64[BD2_];
__device__ float g_u48[BD1_];
__device__ float g_w48[BD1_];
__device__ float g_zfin[BD1_];
__device__ float g_n1[B_ * C2 * 2];   // (scale, shift) per (b,c) for gn1
__device__ float g_n2[B_ * C1 * 2];
__device__ float g_n3[B_ * C1 * 2];
__device__ float g_bnP[C1 * 2];
__device__ float g_Hm[B_ * MH * MH];
__device__ float g_alpha[B_ * MH];

// ---------------- elementwise helpers ----------------
__global__ void zero_k(float* p, int n) {
    int i = blockIdx.x * blockDim.x + threadIdx.x;
    if (i < n) p[i] = 0.f;
}
__global__ void copy_k(float* dst, const float* src, int n) {
    int i = blockIdx.x * blockDim.x + threadIdx.x;
    if (i < n) dst[i] = src[i];
}

// ---------------- conv0: 1 -> 48, 3x3 SAME, + bias ----------------
__global__ void conv0_k(const float* __restrict__ x, const float* __restrict__ w,
                        const float* __restrict__ bias, float* __restrict__ out) {
    __shared__ float ws[48 * 9];
    __shared__ float bs[48];
    for (int i = threadIdx.x; i < 48 * 9; i += blockDim.x) ws[i] = w[i];
    for (int i = threadIdx.x; i < 48; i += blockDim.x) bs[i] = bias[i];
    __syncthreads();
    int t = blockIdx.x * blockDim.x + threadIdx.x;
    if (t >= B_ * HW_) return;
    int b = t / HW_;
    int pix = t % HW_;
    int y = pix / W_, xx = pix % W_;
    const float* xp = x + (size_t)b * HW_;
    float iv[9];
    int k = 0;
#pragma unroll
    for (int dy = 0; dy < 3; dy++)
#pragma unroll
        for (int dx = 0; dx < 3; dx++) {
            int gy = y + dy - 1, gx = xx + dx - 1;
            iv[k++] = (gy >= 0 && gy < H_ && gx >= 0 && gx < W_) ? xp[gy * W_ + gx] : 0.f;
        }
    for (int o = 0; o < 48; o++) {
        float a = bs[o];
#pragma unroll
        for (int kk = 0; kk < 9; kk++) a += ws[o * 9 + kk] * iv[kk];
        out[((size_t)b * 48 + o) * HW_ + pix] = a;
    }
}

// ---------------- BatchNorm (training-mode, batch stats) ----------------
__global__ void bn_reduce_k(const float* __restrict__ data, const float* __restrict__ gma,
                            const float* __restrict__ bta, float* __restrict__ bnP) {
    int c = blockIdx.x;
    double s = 0, s2 = 0;
    const int N = B_ * HW_;
    for (int t = threadIdx.x; t < N; t += blockDim.x) {
        int b = t / HW_, i = t % HW_;
        float v = data[((size_t)b * C1 + c) * HW_ + i];
        s += v; s2 += (double)v * v;
    }
    __shared__ double sh1[512], sh2[512];
    sh1[threadIdx.x] = s; sh2[threadIdx.x] = s2;
    __syncthreads();
    for (int st = 256; st > 0; st >>= 1) {
        if (threadIdx.x < st) { sh1[threadIdx.x] += sh1[threadIdx.x + st]; sh2[threadIdx.x] += sh2[threadIdx.x + st]; }
        __syncthreads();
    }
    if (threadIdx.x == 0) {
        double mu = sh1[0] / N;
        double var = sh2[0] / N - mu * mu;
        float rs = rsqrtf((float)var + EPS_);
        float scl = gma[c] * rs;
        bnP[c * 2] = scl;
        bnP[c * 2 + 1] = bta[c] - (float)mu * scl;
    }
}
__global__ void bn_apply_k(const float* __restrict__ in, const float* __restrict__ bnP,
                           float* __restrict__ out) {
    int idx = blockIdx.x * blockDim.x + threadIdx.x;
    if (idx >= BD1_) return;
    int c = (idx / HW_) % C1;
    out[idx] = in[idx] * bnP[c * 2] + bnP[c * 2 + 1];
}

// ---------------- GroupNorm stats (NG=8 groups) ----------------
template <int C>
__global__ void gn_reduce_k(const float* __restrict__ data, const float* __restrict__ gma,
                            const float* __restrict__ bta, float* __restrict__ normP) {
    const int g = blockIdx.x, b = blockIdx.y;
    const int cpg = C / 8;
    const int Nel = cpg * HW_;
    const float* base = data + ((size_t)b * C + g * cpg) * HW_;
    double s = 0, s2 = 0;
    for (int i = threadIdx.x; i < Nel; i += blockDim.x) {
        float v = base[i];
        s += v; s2 += (double)v * v;
    }
    __shared__ double sh1[512], sh2[512];
    sh1[threadIdx.x] = s; sh2[threadIdx.x] = s2;
    __syncthreads();
    for (int st = 256; st > 0; st >>= 1) {
        if (threadIdx.x < st) { sh1[threadIdx.x] += sh1[threadIdx.x + st]; sh2[threadIdx.x] += sh2[threadIdx.x + st]; }
        __syncthreads();
    }
    if (threadIdx.x == 0) {
        double mu = sh1[0] / Nel;
        double var = sh2[0] / Nel - mu * mu;
        float rs = rsqrtf((float)var + EPS_);
        for (int j = 0; j < cpg; j++) {
            int c = g * cpg + j;
            float scl = gma[c] * rs;
            normP[(b * C + c) * 2] = scl;
            normP[(b * C + c) * 2 + 1] = bta[c] - (float)mu * scl;
        }
    }
}

// ---------------- tiled direct 3x3 conv (SAME, stride 1) ----------------
// block: 50x5 threads; each thread: 4 px along W, OCB out channels.
// NORMIN: normalize input on tile load (zero padding stays zero -> matches conv(gn(x))).
// ADDRES: out = conv + res.  RELU: relu on store.
template <int CIN, int OCB, bool RELU, bool NORMIN, bool ADDRES>
__global__ __launch_bounds__(256, 2) void conv3x3_k(
    const float* __restrict__ in, const float* __restrict__ wgt,
    const float* __restrict__ normP, const float* __restrict__ res,
    float* __restrict__ out) {
    __shared__ float ws[OCB * CIN * 9];
    __shared__ float tile[7][204];
    const int b = blockIdx.z;
    const int ocb = blockIdx.y * OCB;
    const int OC_TOTAL = gridDim.y * OCB;
    const int y0 = blockIdx.x * 5;
    const int tx = threadIdx.x;   // 0..49
    const int ty = threadIdx.y;   // 0..4
    const int tid = ty * 50 + tx;

    for (int i = tid; i < OCB * CIN * 9; i += 250) ws[i] = wgt[ocb * CIN * 9 + i];

    float acc[OCB][4];
#pragma unroll
    for (int o = 0; o < OCB; o++)
#pragma unroll
        for (int p = 0; p < 4; p++) acc[o][p] = 0.f;

    const int xb = tx * 4;
    const int yy = y0 + ty;

    for (int c = 0; c < CIN; c++) {
        __syncthreads();
        const float* inp = in + ((size_t)b * CIN + c) * HW_;
        float sc = 1.f, shf = 0.f;
        if (NORMIN) { sc = normP[(b * CIN + c) * 2]; shf = normP[(b * CIN + c) * 2 + 1]; }
        for (int i = tid; i < 7 * 202; i += 250) {
            int r = i / 202, col = i % 202;
            int gy = y0 - 1 + r, gx = col - 1;
            float v = 0.f;
            if (gy >= 0 && gy < H_ && gx >= 0 && gx < W_) {
                v = inp[gy * W_ + gx];
                if (NORMIN) v = v * sc + shf;
            }
            tile[r][col] = v;
        }
        __syncthreads();
        float iv[3][6];
#pragma unroll
        for (int r = 0; r < 3; r++) {
            float4 v4 = *reinterpret_cast<const float4*>(&tile[ty + r][xb]);
            iv[r][0] = v4.x; iv[r][1] = v4.y; iv[r][2] = v4.z; iv[r][3] = v4.w;
            iv[r][4] = tile[ty + r][xb + 4];
            iv[r][5] = tile[ty + r][xb + 5];
        }
#pragma unroll
        for (int o = 0; o < OCB; o++) {
            const float* wp = &ws[(o * CIN + c) * 9];
            float w0 = wp[0], w1 = wp[1], w2 = wp[2], w3 = wp[3], w4 = wp[4],
                  w5 = wp[5], w6 = wp[6], w7 = wp[7], w8 = wp[8];
#pragma unroll
            for (int p = 0; p < 4; p++) {
                acc[o][p] += w0 * iv[0][p] + w1 * iv[0][p + 1] + w2 * iv[0][p + 2]
                           + w3 * iv[1][p] + w4 * iv[1][p + 1] + w5 * iv[1][p + 2]
                           + w6 * iv[2][p] + w7 * iv[2][p + 1] + w8 * iv[2][p + 2];
            }
        }
    }

    if (yy < H_) {
#pragma unroll
        for (int o = 0; o < OCB; o++) {
            size_t off = ((size_t)b * OC_TOTAL + ocb + o) * HW_ + (size_t)yy * W_ + xb;
            float4 v;
            v.x = acc[o][0]; v.y = acc[o][1]; v.z = acc[o][2]; v.w = acc[o][3];
            if (RELU) {
                v.x = fmaxf(v.x, 0.f); v.y = fmaxf(v.y, 0.f);
                v.z = fmaxf(v.z, 0.f); v.w = fmaxf(v.w, 0.f);
            }
            if (ADDRES) {
                float4 r4 = *reinterpret_cast<const float4*>(res + off);
                v.x += r4.x; v.y += r4.y; v.z += r4.z; v.w += r4.w;
            }
            *reinterpret_cast<float4*>(out + off) = v;
        }
    }
}

// ---------------- f-tail elementwise ----------------
// w = relu(z + gn2(u))
__global__ void k3_k(const float* __restrict__ z, const float* __restrict__ u,
                     const float* __restrict__ n2, float* __restrict__ w) {
    int idx = blockIdx.x * blockDim.x + threadIdx.x;
    if (idx >= BD1_) return;
    int b = idx / D1_;
    int c = (idx / HW_) % C1;
    float gv = u[idx] * n2[(b * C1 + c) * 2] + n2[(b * C1 + c) * 2 + 1];
    w[idx] = fmaxf(z[idx] + gv, 0.f);
}
// out = gn3(w)
__global__ void k4_k(const float* __restrict__ w, const float* __restrict__ n3,
                     float* __restrict__ outF) {
    int idx = blockIdx.x * blockDim.x + threadIdx.x;
    if (idx >= BD1_) return;
    int b = idx / D1_;
    int c = (idx / HW_) % C1;
    outF[idx] = w[idx] * n3[(b * C1 + c) * 2] + n3[(b * C1 + c) * 2 + 1];
}

// ---------------- Anderson: Gram, solve, combine ----------------
template <int N>
__global__ void gram_k() {
    constexpr int NP = N * (N + 1) / 2;
    const int b = blockIdx.y;
    const int chunk = blockIdx.x;           // 48 chunks
    const int per = D1_ / 48;               // 25600
    const size_t base = (size_t)b * D1_ + (size_t)chunk * per;
    float acc[NP];
#pragma unroll
    for (int p = 0; p < NP; p++) acc[p] = 0.f;
    for (int i = threadIdx.x; i < per; i += 256) {
        float gv[N];
#pragma unroll
        for (int s = 0; s < N; s++)
            gv[s] = g_F[(size_t)s * BD1_ + base + i] - g_X[(size_t)s * BD1_ + base + i];
        int p = 0;
#pragma unroll
        for (int a2 = 0; a2 < N; a2++)
#pragma unroll
            for (int c2 = 0; c2 <= a2; c2++) acc[p++] += gv[a2] * gv[c2];
    }
    __shared__ float red[256];
    int p = 0;
    for (int a2 = 0; a2 < N; a2++)
        for (int c2 = 0; c2 <= a2; c2++) {
            red[threadIdx.x] = acc[p];
            __syncthreads();
            for (int st = 128; st > 0; st >>= 1) {
                if (threadIdx.x < st) red[threadIdx.x] += red[threadIdx.x + st];
                __syncthreads();
            }
            if (threadIdx.x == 0) {
                atomicAdd(&g_Hm[(b * MH + a2) * MH + c2], red[0]);
                if (a2 != c2) atomicAdd(&g_Hm[(b * MH + c2) * MH + a2], red[0]);
            }
            __syncthreads();
            p++;
        }
}

__global__ void solve_k(int n) {
    int b = threadIdx.x;
    if (b >= B_) return;
    const int m = n + 1;
    double A[6][7];
    for (int i = 0; i < m; i++)
        for (int j = 0; j < m; j++) A[i][j] = 0.0;
    for (int j = 1; j < m; j++) { A[0][j] = 1.0; A[j][0] = 1.0; }
    for (int i = 1; i < m; i++)
        for (int j = 1; j < m; j++)
            A[i][j] = (double)g_Hm[(b * MH + (i - 1)) * MH + (j - 1)] + (i == j ? 1e-4 : 0.0);
    for (int i = 0; i < m; i++) A[i][m] = (i == 0) ? 1.0 : 0.0;
    // Gaussian elimination with partial pivoting
    for (int col = 0; col < m; col++) {
        int piv = col;
        double best = fabs(A[col][col]);
        for (int r = col + 1; r < m; r++)
            if (fabs(A[r][col]) > best) { best = fabs(A[r][col]); piv = r; }
        if (piv != col)
            for (int j = col; j <= m; j++) { double t = A[col][j]; A[col][j] = A[piv][j]; A[piv][j] = t; }
        double d = A[col][col];
        for (int r = col + 1; r < m; r++) {
            double f = A[r][col] / d;
            for (int j = col; j <= m; j++) A[r][j] -= f * A[col][j];
        }
    }
    double xv[6];
    for (int r = m - 1; r >= 0; r--) {
        double s = A[r][m];
        for (int j = r + 1; j < m; j++) s -= A[r][j] * xv[j];
        xv[r] = s / A[r][r];
    }
    for (int i = 0; i < n; i++) g_alpha[b * MH + i] = (float)xv[i + 1];
}

template <int N>
__global__ void combine_k(int slot) {
    int idx = blockIdx.x * blockDim.x + threadIdx.x;
    if (idx >= BD1_) return;
    int b = idx / D1_;
    float v = 0.f;
#pragma unroll
    for (int s = 0; s < N; s++) v += g_alpha[b * MH + s] * g_F[(size_t)s * BD1_ + idx];
    g_X[(size_t)slot * BD1_ + idx] = v;
}

// ---------------- final Linear(200 -> 10) on last dim ----------------
__global__ void fc_k(const float* __restrict__ z, const float* __restrict__ fw,
                     const float* __restrict__ fb, float* __restrict__ out) {
    __shared__ float ws[10 * 200];
    __shared__ float bb[10];
    for (int i = threadIdx.x; i < 2000; i += 256) ws[i] = fw[i];
    if (threadIdx.x < 10) bb[threadIdx.x] = fb[threadIdx.x];
    __syncthreads();
    int warp = threadIdx.x >> 5, lane = threadIdx.x & 31;
    int row = blockIdx.x * 8 + warp;                 // rows = B*48*H = 49152
    if (row >= B_ * C1 * H_) return;
    const float* zr = z + (size_t)row * W_;
    float p[10];
#pragma unroll
    for (int o = 0; o < 10; o++) p[o] = 0.f;
    for (int col = lane; col < W_; col += 32) {
        float v = zr[col];
#pragma unroll
        for (int o = 0; o < 10; o++) p[o] += v * ws[o * 200 + col];
    }
#pragma unroll
    for (int o = 0; o < 10; o++) {
        float v = p[o];
        for (int off = 16; off > 0; off >>= 1) v += __shfl_down_sync(0xffffffffu, v, off);
        if (lane == 0) out[(size_t)row * 10 + o] = v + bb[o];
    }
}

// ---------------- host orchestration ----------------
struct FParams {
    const float *conv1_w, *conv2_w;
    const float *gn1_g, *gn1_b, *gn2_g, *gn2_b, *gn3_g, *gn3_b;
    float *t64, *u48, *w48, *n1, *n2, *n3;
    const float* h;
};

static void run_f(const float* zin, float* fout, const FParams& P) {
    dim3 cb(50, 5, 1);
    const int EB = BD1_ / 256;  // 38400, exact
    conv3x3_k<48, 8, true, false, false><<<dim3(26, 8, 8), cb>>>(zin, P.conv1_w, nullptr, nullptr, P.t64);
    gn_reduce_k<64><<<dim3(8, 8), 512>>>(P.t64, P.gn1_g, P.gn1_b, P.n1);
    conv3x3_k<64, 8, false, true, true><<<dim3(26, 6, 8), cb>>>(P.t64, P.conv2_w, P.n1, P.h, P.u48);
    gn_reduce_k<48><<<dim3(8, 8), 512>>>(P.u48, P.gn2_g, P.gn2_b, P.n2);
    k3_k<<<EB, 256>>>(zin, P.u48, P.n2, P.w48);
    gn_reduce_k<48><<<dim3(8, 8), 512>>>(P.w48, P.gn3_g, P.gn3_b, P.n3);
    k4_k<<<EB, 256>>>(P.w48, P.n3, fout);
}

extern "C" void kernel_launch(void* const* d_in, const int* in_sizes, int n_in,
                              void* d_out, int out_size) {
    const float* x       = (const float*)d_in[0];
    const float* conv0_w = (const float*)d_in[1];
    const float* conv0_b = (const float*)d_in[2];
    const float* bn_g    = (const float*)d_in[3];
    const float* bn_b    = (const float*)d_in[4];
    const float* conv1_w = (const float*)d_in[5];
    const float* conv2_w = (const float*)d_in[6];
    const float* gn1_g   = (const float*)d_in[7];
    const float* gn1_b   = (const float*)d_in[8];
    const float* gn2_g   = (const float*)d_in[9];
    const float* gn2_b   = (const float*)d_in[10];
    const float* gn3_g   = (const float*)d_in[11];
    const float* gn3_b   = (const float*)d_in[12];
    const float* fc_w    = (const float*)d_in[13];
    const float* fc_b    = (const float*)d_in[14];
    float* out = (float*)d_out;

    float *pX, *pF, *ph, *pt64, *pu48, *pw48, *pzfin, *pn1, *pn2, *pn3, *pbnP, *pHm;
    cudaGetSymbolAddress((void**)&pX, g_X);
    cudaGetSymbolAddress((void**)&pF, g_F);
    cudaGetSymbolAddress((void**)&ph, g_h);
    cudaGetSymbolAddress((void**)&pt64, g_t64);
    cudaGetSymbolAddress((void**)&pu48, g_u48);
    cudaGetSymbolAddress((void**)&pw48, g_w48);
    cudaGetSymbolAddress((void**)&pzfin, g_zfin);
    cudaGetSymbolAddress((void**)&pn1, g_n1);
    cudaGetSymbolAddress((void**)&pn2, g_n2);
    cudaGetSymbolAddress((void**)&pn3, g_n3);
    cudaGetSymbolAddress((void**)&pbnP, g_bnP);
    cudaGetSymbolAddress((void**)&pHm, g_Hm);

    FParams P;
    P.conv1_w = conv1_w; P.conv2_w = conv2_w;
    P.gn1_g = gn1_g; P.gn1_b = gn1_b;
    P.gn2_g = gn2_g; P.gn2_b = gn2_b;
    P.gn3_g = gn3_g; P.gn3_b = gn3_b;
    P.t64 = pt64; P.u48 = pu48; P.w48 = pw48;
    P.n1 = pn1; P.n2 = pn2; P.n3 = pn3;
    P.h = ph;

    const int EB = BD1_ / 256;

    // h = batch_norm(conv0(x) + b)
    conv0_k<<<(B_ * HW_) / 256, 256>>>(x, conv0_w, conv0_b, pu48);
    bn_reduce_k<<<48, 512>>>(pu48, bn_g, bn_b, pbnP);
    bn_apply_k<<<EB, 256>>>(pu48, pbnP, ph);

    // Anderson init: X0 = 0; F0 = f(X0); X1 = F0; F1 = f(X1)
    zero_k<<<EB, 256>>>(pX, BD1_);
    run_f(pX, pF, P);
    copy_k<<<EB, 256>>>(pX + (size_t)BD1_, pF, BD1_);
    run_f(pX + (size_t)BD1_, pF + (size_t)BD1_, P);

    for (int k = 2; k < MAXIT; k++) {
        int n = (k < MH) ? k : MH;
        int s = k % MH;
        zero_k<<<1, 256>>>(pHm, B_ * MH * MH);
        switch (n) {
            case 2: gram_k<2><<<dim3(48, 8), 256>>>(); break;
            case 3: gram_k<3><<<dim3(48, 8), 256>>>(); break;
            case 4: gram_k<4><<<dim3(48, 8), 256>>>(); break;
            default: gram_k<5><<<dim3(48, 8), 256>>>(); break;
        }
        solve_k<<<1, 8>>>(n);
        switch (n) {
            case 2: combine_k<2><<<EB, 256>>>(s); break;
            case 3: combine_k<3><<<EB, 256>>>(s); break;
            case 4: combine_k<4><<<EB, 256>>>(s); break;
            default: combine_k<5><<<EB, 256>>>(s); break;
        }
        run_f(pX + (size_t)s * BD1_, pF + (size_t)s * BD1_, P);
    }

    // z_star = X[(MAXIT-1) % MH] = X[4]; z = f(z_star)
    run_f(pX + (size_t)4 * BD1_, pzfin, P);

    // out[b,c,h,o] = sum_w z[b,c,h,w] * fc_w[o,w] + fc_b[o]
    fc_k<<<(B_ * C1 * H_) / 8, 256>>>(pzfin, fc_w, fc_b, out);
    (void)in_sizes; (void)n_in; (void)out_size;
}

// round 2
// speedup vs baseline: 2.0328x; 2.0328x over previous
#include <cuda_runtime.h>
#include <math.h>

// ---------------- problem constants ----------------
static constexpr int B_   = 8;
static constexpr int H_   = 128;
static constexpr int W_   = 200;
static constexpr int HW_  = H_ * W_;          // 25600
static constexpr int C1   = 48;
static constexpr int C2   = 64;
static constexpr int D1_  = C1 * HW_;         // 1228800
static constexpr int BD1_ = B_ * D1_;         // 9830400
static constexpr int BD2_ = B_ * C2 * HW_;    // 13107200
static constexpr int MH   = 5;
static constexpr int MAXIT = 25;
static constexpr float EPS_ = 1e-5f;
static constexpr int D1Q  = D1_ / 4;          // 307200
static constexpr int BD1Q = BD1_ / 4;         // 2457600
static constexpr int HWQ  = HW_ / 4;          // 6400
static constexpr int NCHUNK = 100;            // gram chunks per batch
static constexpr int PER4   = D1Q / NCHUNK;   // 3072 float4 per chunk

// ---------------- scratch (device globals; no allocation allowed) ----------
__device__ alignas(16) float g_X[(size_t)MH * BD1_];
__device__ alignas(16) float g_F[(size_t)MH * BD1_];
__device__ alignas(16) float g_G[(size_t)MH * BD1_];
__device__ alignas(16) float g_h[BD1_];
__device__ alignas(16) float g_t64[BD2_];
__device__ alignas(16) float g_u48[BD1_];
__device__ alignas(16) float g_w48[BD1_];
__device__ alignas(16) float g_zfin[BD1_];
__device__ float g_n1[B_ * C2 * 2];
__device__ float g_n2[B_ * C1 * 2];
__device__ float g_n3[B_ * C1 * 2];
__device__ float g_bnP[C1 * 2];
__device__ float g_Hm[B_ * MH * MH];
__device__ float g_alpha[B_ * MH];
__device__ float g_Hpart[B_ * NCHUNK * 15];
__device__ alignas(16) float g_w1p[C2 * C1 * 12];   // packed conv1 weights
__device__ alignas(16) float g_w2p[C1 * C2 * 12];   // packed conv2 weights

// ---------------- small helpers ----------------
__global__ void zero4_k(float4* p, int n4) {
    int i = blockIdx.x * blockDim.x + threadIdx.x;
    if (i < n4) p[i] = make_float4(0.f, 0.f, 0.f, 0.f);
}
__global__ void copy4_k(float4* dst, const float4* src, int n4) {
    int i = blockIdx.x * blockDim.x + threadIdx.x;
    if (i < n4) dst[i] = src[i];
}
__global__ void pack_w_k(const float* __restrict__ w, float* __restrict__ wp, int n) {
    int i = blockIdx.x * blockDim.x + threadIdx.x;   // over OC*CIN
    if (i >= n) return;
#pragma unroll
    for (int k = 0; k < 9; k++) wp[i * 12 + k] = w[i * 9 + k];
    wp[i * 12 + 9] = 0.f; wp[i * 12 + 10] = 0.f; wp[i * 12 + 11] = 0.f;
}

// ---------------- conv0: 1 -> 48, 3x3 SAME, + bias ----------------
__global__ void conv0_k(const float* __restrict__ x, const float* __restrict__ w,
                        const float* __restrict__ bias, float* __restrict__ out) {
    __shared__ float ws[48 * 9];
    __shared__ float bs[48];
    for (int i = threadIdx.x; i < 48 * 9; i += blockDim.x) ws[i] = w[i];
    for (int i = threadIdx.x; i < 48; i += blockDim.x) bs[i] = bias[i];
    __syncthreads();
    int t = blockIdx.x * blockDim.x + threadIdx.x;
    if (t >= B_ * HW_) return;
    int b = t / HW_;
    int pix = t % HW_;
    int y = pix / W_, xx = pix % W_;
    const float* xp = x + (size_t)b * HW_;
    float iv[9];
    int k = 0;
#pragma unroll
    for (int dy = 0; dy < 3; dy++)
#pragma unroll
        for (int dx = 0; dx < 3; dx++) {
            int gy = y + dy - 1, gx = xx + dx - 1;
            iv[k++] = (gy >= 0 && gy < H_ && gx >= 0 && gx < W_) ? xp[gy * W_ + gx] : 0.f;
        }
    for (int o = 0; o < 48; o++) {
        float a = bs[o];
#pragma unroll
        for (int kk = 0; kk < 9; kk++) a += ws[o * 9 + kk] * iv[kk];
        out[((size_t)b * 48 + o) * HW_ + pix] = a;
    }
}

// ---------------- BatchNorm reduce (batch stats) ----------------
__global__ void bn_reduce_k(const float* __restrict__ data, const float* __restrict__ gma,
                            const float* __restrict__ bta, float* __restrict__ bnP) {
    int c = blockIdx.x;
    double s = 0, s2 = 0;
    const int N4 = B_ * HWQ;   // 51200
    const float4* d4 = reinterpret_cast<const float4*>(data);
    for (int t = threadIdx.x; t < N4; t += blockDim.x) {
        int b = t / HWQ, i = t % HWQ;
        float4 v = d4[(size_t)(b * C1 + c) * HWQ + i];
        s  += (double)(v.x + v.y + v.z + v.w);
        s2 += (double)(v.x * v.x + v.y * v.y + v.z * v.z + v.w * v.w);
    }
    __shared__ double sh1[512], sh2[512];
    sh1[threadIdx.x] = s; sh2[threadIdx.x] = s2;
    __syncthreads();
    for (int st = 256; st > 0; st >>= 1) {
        if (threadIdx.x < st) { sh1[threadIdx.x] += sh1[threadIdx.x + st]; sh2[threadIdx.x] += sh2[threadIdx.x + st]; }
        __syncthreads();
    }
    if (threadIdx.x == 0) {
        const int N = B_ * HW_;
        double mu = sh1[0] / N;
        double var = sh2[0] / N - mu * mu;
        float rs = rsqrtf((float)var + EPS_);
        float scl = gma[c] * rs;
        bnP[c * 2] = scl;
        bnP[c * 2 + 1] = bta[c] - (float)mu * scl;
    }
}
__global__ void bn_apply_k(const float* __restrict__ in, const float* __restrict__ bnP,
                           float* __restrict__ out) {
    int i = blockIdx.x * blockDim.x + threadIdx.x;  // over BD1Q
    if (i >= BD1Q) return;
    int c = (i / HWQ) % C1;
    float sc = bnP[c * 2], sh = bnP[c * 2 + 1];
    float4 v = reinterpret_cast<const float4*>(in)[i];
    v.x = v.x * sc + sh; v.y = v.y * sc + sh; v.z = v.z * sc + sh; v.w = v.w * sc + sh;
    reinterpret_cast<float4*>(out)[i] = v;
}

// ---------------- GroupNorm stats (NG=8) ----------------
template <int C>
__global__ void gn_reduce_k(const float* __restrict__ data, const float* __restrict__ gma,
                            const float* __restrict__ bta, float* __restrict__ normP) {
    const int g = blockIdx.x, b = blockIdx.y;
    const int cpg = C / 8;
    const int N4 = cpg * HWQ;
    const float4* base = reinterpret_cast<const float4*>(data) + (size_t)(b * C + g * cpg) * HWQ;
    double s = 0, s2 = 0;
    for (int i = threadIdx.x; i < N4; i += blockDim.x) {
        float4 v = base[i];
        s  += (double)(v.x + v.y + v.z + v.w);
        s2 += (double)(v.x * v.x + v.y * v.y + v.z * v.z + v.w * v.w);
    }
    __shared__ double sh1[512], sh2[512];
    sh1[threadIdx.x] = s; sh2[threadIdx.x] = s2;
    __syncthreads();
    for (int st = 256; st > 0; st >>= 1) {
        if (threadIdx.x < st) { sh1[threadIdx.x] += sh1[threadIdx.x + st]; sh2[threadIdx.x] += sh2[threadIdx.x + st]; }
        __syncthreads();
    }
    if (threadIdx.x == 0) {
        const int Nel = cpg * HW_;
        double mu = sh1[0] / Nel;
        double var = sh2[0] / Nel - mu * mu;
        float rs = rsqrtf((float)var + EPS_);
        for (int j = 0; j < cpg; j++) {
            int c = g * cpg + j;
            float scl = gma[c] * rs;
            normP[(b * C + c) * 2] = scl;
            normP[(b * C + c) * 2 + 1] = bta[c] - (float)mu * scl;
        }
    }
}

// ---------------- tiled direct 3x3 conv, double-buffered ----------------
// block 50x5, 4 px/thread along W, OCB out channels. Weights packed [OC][CIN][12].
template <int CIN, int OCB, bool RELU, bool NORMIN, bool ADDRES>
__global__ __launch_bounds__(256, 2) void conv3x3_k(
    const float* __restrict__ in, const float* __restrict__ wp,
    const float* __restrict__ normP, const float* __restrict__ res,
    float* __restrict__ out) {
    __shared__ alignas(16) float ws[OCB * CIN * 12];
    __shared__ alignas(16) float tile[2][7 * 204];
    const int b = blockIdx.z;
    const int ocb = blockIdx.y * OCB;
    const int OC_TOTAL = gridDim.y * OCB;
    const int y0 = blockIdx.x * 5;
    const int tx = threadIdx.x;   // 0..49
    const int ty = threadIdx.y;   // 0..4
    const int tid = ty * 50 + tx;

    // weights -> smem via float4
    {
        const float4* wg4 = reinterpret_cast<const float4*>(wp + (size_t)ocb * CIN * 12);
        float4* ws4 = reinterpret_cast<float4*>(ws);
        for (int i = tid; i < OCB * CIN * 3; i += 250) ws4[i] = wg4[i];
    }

    // precompute tile-load slots (6 per thread, 1414 total)
    int goff[6], sidx[6];
    bool vld[6], inb[6];
#pragma unroll
    for (int k = 0; k < 6; k++) {
        int e = tid + k * 250;
        vld[k] = (e < 1414);
        int ee = vld[k] ? e : 0;
        int r = ee / 202, col = ee % 202;
        int gy = y0 - 1 + r, gx = col - 1;
        inb[k] = vld[k] && (gy >= 0 && gy < H_ && gx >= 0 && gx < W_);
        goff[k] = inb[k] ? gy * W_ + gx : 0;
        sidx[k] = r * 204 + col;
    }

    const float* inB = in + (size_t)b * CIN * HW_;

    // load channel 0 into buffer 0
    {
        float sc = 1.f, sh = 0.f;
        if (NORMIN) { sc = normP[(b * CIN) * 2]; sh = normP[(b * CIN) * 2 + 1]; }
#pragma unroll
        for (int k = 0; k < 6; k++) {
            float v = inb[k] ? inB[goff[k]] : 0.f;
            if (NORMIN) v = inb[k] ? v * sc + sh : 0.f;
            if (vld[k]) tile[0][sidx[k]] = v;
        }
    }
    __syncthreads();

    float acc[OCB][4];
#pragma unroll
    for (int o = 0; o < OCB; o++)
#pragma unroll
        for (int p = 0; p < 4; p++) acc[o][p] = 0.f;

    const int xb = tx * 4;
    const int yy = y0 + ty;

    for (int c = 0; c < CIN; c++) {
        const float* cur = &tile[c & 1][0];
        // prefetch channel c+1 into registers
        float rv[6];
        float scN = 1.f, shN = 0.f;
        const bool more = (c + 1 < CIN);
        if (more) {
            if (NORMIN) {
                scN = normP[(b * CIN + c + 1) * 2];
                shN = normP[(b * CIN + c + 1) * 2 + 1];
            }
            const float* p = inB + (size_t)(c + 1) * HW_;
#pragma unroll
            for (int k = 0; k < 6; k++) rv[k] = inb[k] ? __ldg(p + goff[k]) : 0.f;
        }

        // compute channel c
        float iv[3][6];
#pragma unroll
        for (int r = 0; r < 3; r++) {
            const float* rowp = cur + (ty + r) * 204 + xb;
            float4 v4 = *reinterpret_cast<const float4*>(rowp);
            iv[r][0] = v4.x; iv[r][1] = v4.y; iv[r][2] = v4.z; iv[r][3] = v4.w;
            iv[r][4] = rowp[4];
            iv[r][5] = rowp[5];
        }
        const float4* wb4 = reinterpret_cast<const float4*>(ws) + c * 3;
#pragma unroll
        for (int o = 0; o < OCB; o++) {
            float4 wA = wb4[o * CIN * 3 + 0];
            float4 wB = wb4[o * CIN * 3 + 1];
            float4 wC = wb4[o * CIN * 3 + 2];
#pragma unroll
            for (int p = 0; p < 4; p++) {
                acc[o][p] += wA.x * iv[0][p] + wA.y * iv[0][p + 1] + wA.z * iv[0][p + 2]
                           + wA.w * iv[1][p] + wB.x * iv[1][p + 1] + wB.y * iv[1][p + 2]
                           + wB.z * iv[2][p] + wB.w * iv[2][p + 1] + wC.x * iv[2][p + 2];
            }
        }

        // store prefetched channel into alternate buffer
        if (more) {
            float* nt = &tile[(c + 1) & 1][0];
#pragma unroll
            for (int k = 0; k < 6; k++) {
                float v = rv[k];
                if (NORMIN) v = inb[k] ? v * scN + shN : 0.f;
                if (vld[k]) nt[sidx[k]] = v;
            }
        }
        __syncthreads();
    }

    if (yy < H_) {
#pragma unroll
        for (int o = 0; o < OCB; o++) {
            size_t off = ((size_t)b * OC_TOTAL + ocb + o) * HW_ + (size_t)yy * W_ + xb;
            float4 v;
            v.x = acc[o][0]; v.y = acc[o][1]; v.z = acc[o][2]; v.w = acc[o][3];
            if (RELU) {
                v.x = fmaxf(v.x, 0.f); v.y = fmaxf(v.y, 0.f);
                v.z = fmaxf(v.z, 0.f); v.w = fmaxf(v.w, 0.f);
            }
            if (ADDRES) {
                float4 r4 = *reinterpret_cast<const float4*>(res + off);
                v.x += r4.x; v.y += r4.y; v.z += r4.z; v.w += r4.w;
            }
            *reinterpret_cast<float4*>(out + off) = v;
        }
    }
}

// ---------------- f-tail elementwise (float4) ----------------
// w = relu(z + gn2(u))
__global__ void k3_k(const float* __restrict__ z, const float* __restrict__ u,
                     const float* __restrict__ n2, float* __restrict__ w) {
    int i = blockIdx.x * blockDim.x + threadIdx.x;  // BD1Q
    if (i >= BD1Q) return;
    int b = i / D1Q;
    int c = (i / HWQ) % C1;
    float sc = n2[(b * C1 + c) * 2], sh = n2[(b * C1 + c) * 2 + 1];
    float4 uv = reinterpret_cast<const float4*>(u)[i];
    float4 zv = reinterpret_cast<const float4*>(z)[i];
    float4 o;
    o.x = fmaxf(zv.x + uv.x * sc + sh, 0.f);
    o.y = fmaxf(zv.y + uv.y * sc + sh, 0.f);
    o.z = fmaxf(zv.z + uv.z * sc + sh, 0.f);
    o.w = fmaxf(zv.w + uv.w * sc + sh, 0.f);
    reinterpret_cast<float4*>(w)[i] = o;
}
// F = gn3(w); optionally G = F - X
template <bool GOUT>
__global__ void k4_k(const float* __restrict__ w, const float* __restrict__ n3,
                     const float* __restrict__ xslot, float* __restrict__ fout,
                     float* __restrict__ gout) {
    int i = blockIdx.x * blockDim.x + threadIdx.x;  // BD1Q
    if (i >= BD1Q) return;
    int b = i / D1Q;
    int c = (i / HWQ) % C1;
    float sc = n3[(b * C1 + c) * 2], sh = n3[(b * C1 + c) * 2 + 1];
    float4 wv = reinterpret_cast<const float4*>(w)[i];
    float4 f;
    f.x = wv.x * sc + sh; f.y = wv.y * sc + sh;
    f.z = wv.z * sc + sh; f.w = wv.w * sc + sh;
    reinterpret_cast<float4*>(fout)[i] = f;
    if (GOUT) {
        float4 xv = reinterpret_cast<const float4*>(xslot)[i];
        float4 g;
        g.x = f.x - xv.x; g.y = f.y - xv.y; g.z = f.z - xv.z; g.w = f.w - xv.w;
        reinterpret_cast<float4*>(gout)[i] = g;
    }
}

// ---------------- Anderson: Gram (2-stage, deterministic) ----------------
template <int N>
__global__ void gram_k() {
    constexpr int NP = N * (N + 1) / 2;
    const int b = blockIdx.y;
    const int chunk = blockIdx.x;                  // NCHUNK
    const size_t base = (size_t)b * D1Q + (size_t)chunk * PER4;
    const float4* G4 = reinterpret_cast<const float4*>(g_G);
    float acc[NP];
#pragma unroll
    for (int p = 0; p < NP; p++) acc[p] = 0.f;
    for (int it = 0; it < PER4 / 256; it++) {
        int i = threadIdx.x + it * 256;
        float4 gv[N];
#pragma unroll
        for (int s = 0; s < N; s++) gv[s] = G4[(size_t)s * BD1Q + base + i];
        int p = 0;
#pragma unroll
        for (int a2 = 0; a2 < N; a2++)
#pragma unroll
            for (int c2 = 0; c2 <= a2; c2++) {
                acc[p++] += gv[a2].x * gv[c2].x + gv[a2].y * gv[c2].y
                          + gv[a2].z * gv[c2].z + gv[a2].w * gv[c2].w;
            }
    }
    __shared__ float red[15][9];
    int wid = threadIdx.x >> 5, ln = threadIdx.x & 31;
#pragma unroll
    for (int p = 0; p < NP; p++) {
        float v = acc[p];
        for (int off = 16; off > 0; off >>= 1) v += __shfl_down_sync(0xffffffffu, v, off);
        if (ln == 0) red[p][wid] = v;
    }
    __syncthreads();
    if (threadIdx.x < NP) {
        float s = 0.f;
#pragma unroll
        for (int w = 0; w < 8; w++) s += red[threadIdx.x][w];
        g_Hpart[(b * NCHUNK + chunk) * 15 + threadIdx.x] = s;
    }
}

template <int N>
__global__ void hfin_k() {
    constexpr int NP = N * (N + 1) / 2;
    int b = blockIdx.x;
    int p = threadIdx.x;
    if (p >= NP) return;
    // map p -> (i,j), i>=j
    int i = 0, j = 0, q = p;
    for (int a2 = 0; a2 < N; a2++) {
        if (q <= a2) { i = a2; j = q; break; }
        q -= (a2 + 1);
    }
    float s = 0.f;
    for (int ch = 0; ch < NCHUNK; ch++) s += g_Hpart[(b * NCHUNK + ch) * 15 + p];
    g_Hm[(b * MH + i) * MH + j] = s;
    g_Hm[(b * MH + j) * MH + i] = s;
}

__global__ void solve_k(int n) {
    int b = threadIdx.x;
    if (b >= B_) return;
    const int m = n + 1;
    double A[6][7];
    for (int i = 0; i < m; i++)
        for (int j = 0; j < m; j++) A[i][j] = 0.0;
    for (int j = 1; j < m; j++) { A[0][j] = 1.0; A[j][0] = 1.0; }
    for (int i = 1; i < m; i++)
        for (int j = 1; j < m; j++)
            A[i][j] = (double)g_Hm[(b * MH + (i - 1)) * MH + (j - 1)] + (i == j ? 1e-4 : 0.0);
    for (int i = 0; i < m; i++) A[i][m] = (i == 0) ? 1.0 : 0.0;
    for (int col = 0; col < m; col++) {
        int piv = col;
        double best = fabs(A[col][col]);
        for (int r = col + 1; r < m; r++)
            if (fabs(A[r][col]) > best) { best = fabs(A[r][col]); piv = r; }
        if (piv != col)
            for (int j = col; j <= m; j++) { double t = A[col][j]; A[col][j] = A[piv][j]; A[piv][j] = t; }
        double d = A[col][col];
        for (int r = col + 1; r < m; r++) {
            double f = A[r][col] / d;
            for (int j = col; j <= m; j++) A[r][j] -= f * A[col][j];
        }
    }
    double xv[6];
    for (int r = m - 1; r >= 0; r--) {
        double s = A[r][m];
        for (int j = r + 1; j < m; j++) s -= A[r][j] * xv[j];
        xv[r] = s / A[r][r];
    }
    for (int i = 0; i < n; i++) g_alpha[b * MH + i] = (float)xv[i + 1];
}

template <int N>
__global__ void combine_k(int slot) {
    int i = blockIdx.x * blockDim.x + threadIdx.x;  // BD1Q
    if (i >= BD1Q) return;
    int b = i / D1Q;
    const float4* F4 = reinterpret_cast<const float4*>(g_F);
    float4 v = make_float4(0.f, 0.f, 0.f, 0.f);
#pragma unroll
    for (int s = 0; s < N; s++) {
        float a = g_alpha[b * MH + s];
        float4 f = F4[(size_t)s * BD1Q + i];
        v.x += a * f.x; v.y += a * f.y; v.z += a * f.z; v.w += a * f.w;
    }
    reinterpret_cast<float4*>(g_X)[(size_t)slot * BD1Q + i] = v;
}

// ---------------- final Linear(200 -> 10) ----------------
__global__ void fc_k(const float* __restrict__ z, const float* __restrict__ fw,
                     const float* __restrict__ fb, float* __restrict__ out) {
    __shared__ float ws[10 * 200];
    __shared__ float bb[10];
    for (int i = threadIdx.x; i < 2000; i += 256) ws[i] = fw[i];
    if (threadIdx.x < 10) bb[threadIdx.x] = fb[threadIdx.x];
    __syncthreads();
    int warp = threadIdx.x >> 5, lane = threadIdx.x & 31;
    int row = blockIdx.x * 8 + warp;
    if (row >= B_ * C1 * H_) return;
    const float* zr = z + (size_t)row * W_;
    float p[10];
#pragma unroll
    for (int o = 0; o < 10; o++) p[o] = 0.f;
    for (int col = lane; col < W_; col += 32) {
        float v = zr[col];
#pragma unroll
        for (int o = 0; o < 10; o++) p[o] += v * ws[o * 200 + col];
    }
#pragma unroll
    for (int o = 0; o < 10; o++) {
        float v = p[o];
        for (int off = 16; off > 0; off >>= 1) v += __shfl_down_sync(0xffffffffu, v, off);
        if (lane == 0) out[(size_t)row * 10 + o] = v + bb[o];
    }
}

// ---------------- host orchestration ----------------
struct FParams {
    const float *w1p, *w2p;
    const float *gn1_g, *gn1_b, *gn2_g, *gn2_b, *gn3_g, *gn3_b;
    float *t64, *u48, *w48, *n1, *n2, *n3;
    const float* h;
};

static void run_f(const float* zin, const float* xslot, float* fout, float* gout,
                  const FParams& P) {
    dim3 cb(50, 5, 1);
    const int EQ = BD1Q / 256;  // 9600
    conv3x3_k<48, 8, true, false, false><<<dim3(26, 8, 8), cb>>>(zin, P.w1p, nullptr, nullptr, P.t64);
    gn_reduce_k<64><<<dim3(8, 8), 512>>>(P.t64, P.gn1_g, P.gn1_b, P.n1);
    conv3x3_k<64, 8, false, true, true><<<dim3(26, 6, 8), cb>>>(P.t64, P.w2p, P.n1, P.h, P.u48);
    gn_reduce_k<48><<<dim3(8, 8), 512>>>(P.u48, P.gn2_g, P.gn2_b, P.n2);
    k3_k<<<EQ, 256>>>(zin, P.u48, P.n2, P.w48);
    gn_reduce_k<48><<<dim3(8, 8), 512>>>(P.w48, P.gn3_g, P.gn3_b, P.n3);
    if (gout)
        k4_k<true><<<EQ, 256>>>(P.w48, P.n3, xslot, fout, gout);
    else
        k4_k<false><<<EQ, 256>>>(P.w48, P.n3, nullptr, fout, nullptr);
}

extern "C" void kernel_launch(void* const* d_in, const int* in_sizes, int n_in,
                              void* d_out, int out_size) {
    const float* x       = (const float*)d_in[0];
    const float* conv0_w = (const float*)d_in[1];
    const float* conv0_b = (const float*)d_in[2];
    const float* bn_g    = (const float*)d_in[3];
    const float* bn_b    = (const float*)d_in[4];
    const float* conv1_w = (const float*)d_in[5];
    const float* conv2_w = (const float*)d_in[6];
    const float* gn1_g   = (const float*)d_in[7];
    const float* gn1_b   = (const float*)d_in[8];
    const float* gn2_g   = (const float*)d_in[9];
    const float* gn2_b   = (const float*)d_in[10];
    const float* gn3_g   = (const float*)d_in[11];
    const float* gn3_b   = (const float*)d_in[12];
    const float* fc_w    = (const float*)d_in[13];
    const float* fc_b    = (const float*)d_in[14];
    float* out = (float*)d_out;

    float *pX, *pF, *pG, *ph, *pt64, *pu48, *pw48, *pzfin, *pn1, *pn2, *pn3, *pbnP;
    float *pw1p, *pw2p;
    cudaGetSymbolAddress((void**)&pX, g_X);
    cudaGetSymbolAddress((void**)&pF, g_F);
    cudaGetSymbolAddress((void**)&pG, g_G);
    cudaGetSymbolAddress((void**)&ph, g_h);
    cudaGetSymbolAddress((void**)&pt64, g_t64);
    cudaGetSymbolAddress((void**)&pu48, g_u48);
    cudaGetSymbolAddress((void**)&pw48, g_w48);
    cudaGetSymbolAddress((void**)&pzfin, g_zfin);
    cudaGetSymbolAddress((void**)&pn1, g_n1);
    cudaGetSymbolAddress((void**)&pn2, g_n2);
    cudaGetSymbolAddress((void**)&pn3, g_n3);
    cudaGetSymbolAddress((void**)&pbnP, g_bnP);
    cudaGetSymbolAddress((void**)&pw1p, g_w1p);
    cudaGetSymbolAddress((void**)&pw2p, g_w2p);

    FParams P;
    P.w1p = pw1p; P.w2p = pw2p;
    P.gn1_g = gn1_g; P.gn1_b = gn1_b;
    P.gn2_g = gn2_g; P.gn2_b = gn2_b;
    P.gn3_g = gn3_g; P.gn3_b = gn3_b;
    P.t64 = pt64; P.u48 = pu48; P.w48 = pw48;
    P.n1 = pn1; P.n2 = pn2; P.n3 = pn3;
    P.h = ph;

    const int EQ = BD1Q / 256;  // 9600

    // h = batch_norm(conv0(x) + b); weight packing
    conv0_k<<<(B_ * HW_) / 256, 256>>>(x, conv0_w, conv0_b, pu48);
    bn_reduce_k<<<48, 512>>>(pu48, bn_g, bn_b, pbnP);
    bn_apply_k<<<EQ, 256>>>(pu48, pbnP, ph);
    pack_w_k<<<12, 256>>>(conv1_w, pw1p, C2 * C1);
    pack_w_k<<<12, 256>>>(conv2_w, pw2p, C1 * C2);

    // Anderson init
    zero4_k<<<EQ, 256>>>((float4*)pX, BD1Q);
    run_f(pX, pX, pF, pG, P);                                  // F0, G0 = F0 - 0
    copy4_k<<<EQ, 256>>>((float4*)(pX + (size_t)BD1_), (const float4*)pF, BD1Q);  // X1 = F0
    run_f(pX + (size_t)BD1_, pX + (size_t)BD1_, pF + (size_t)BD1_, pG + (size_t)BD1_, P);

    for (int k = 2; k < MAXIT; k++) {
        int n = (k < MH) ? k : MH;
        int s = k % MH;
        switch (n) {
            case 2: gram_k<2><<<dim3(NCHUNK, 8), 256>>>(); hfin_k<2><<<8, 32>>>(); break;
            case 3: gram_k<3><<<dim3(NCHUNK, 8), 256>>>(); hfin_k<3><<<8, 32>>>(); break;
            case 4: gram_k<4><<<dim3(NCHUNK, 8), 256>>>(); hfin_k<4><<<8, 32>>>(); break;
            default: gram_k<5><<<dim3(NCHUNK, 8), 256>>>(); hfin_k<5><<<8, 32>>>(); break;
        }
        solve_k<<<1, 8>>>(n);
        switch (n) {
            case 2: combine_k<2><<<EQ, 256>>>(s); break;
            case 3: combine_k<3><<<EQ, 256>>>(s); break;
            case 4: combine_k<4><<<EQ, 256>>>(s); break;
            default: combine_k<5><<<EQ, 256>>>(s); break;
        }
        run_f(pX + (size_t)s * BD1_, pX + (size_t)s * BD1_,
              pF + (size_t)s * BD1_, pG + (size_t)s * BD1_, P);
    }

    // z_star = X[(MAXIT-1) % MH] = X[4]; z = f(z_star), no G needed
    run_f(pX + (size_t)4 * BD1_, nullptr, pzfin, nullptr, P);

    fc_k<<<(B_ * C1 * H_) / 8, 256>>>(pzfin, fc_w, fc_b, out);
    (void)in_sizes; (void)n_in; (void)out_size;
}